// round 15
// baseline (speedup 1.0000x reference)
#include <cuda_runtime.h>
#include <cuda_fp16.h>
#include <cstdint>

using fp16 = __half;
using h2 = __half2;

#define DEVFN __device__ __forceinline__

// ---------------- problem sizes ----------------
constexpr int B_SZ = 16, SEQ = 2048, DM = 512, DI = 1024, DS = 16;
constexpr int ROWS = B_SZ * SEQ;           // 32768
constexpr int N1 = 2 * DI;                 // 2048
constexpr int N2 = 1152;                   // 1024 dt + 32 (B|C) + 96 pad
constexpr int N3 = DM;                     // 512

// ---------------- scratch globals (fp16 intermediates) ----------------
__device__ __align__(256) fp16  g_xb  [(size_t)ROWS * DM];
__device__ __align__(256) fp16  g_W1  [(size_t)N1 * DM];
__device__ __align__(256) fp16  g_xr  [(size_t)ROWS * N1];   // x_p | silu(res)
__device__ __align__(256) fp16  g_xc  [(size_t)ROWS * DI];
__device__ __align__(256) fp16  g_Wcat[(size_t)N2 * DI];
__device__ __align__(256) float g_b2  [N2];
__device__ __align__(256) fp16  g_dtbc[(size_t)ROWS * N2];
__device__ __align__(256) float g_bc  [(size_t)ROWS * 32];   // B|C f32 for scan
__device__ __align__(256) fp16  g_y2  [(size_t)ROWS * DI];
__device__ __align__(256) fp16  g_W3  [(size_t)N3 * DI];
__device__ __align__(256) float g_opre[(size_t)ROWS * DM];

// ---------------- helpers ----------------
DEVFN float h2f(fp16 v) { return __half2float(v); }
DEVFN fp16  f2h(float v) { return __float2half(v); }
DEVFN float2 h2x(uint32_t u) { h2 t = *reinterpret_cast<h2*>(&u); return __half22float2(t); }
DEVFN uint32_t pack2h(float a, float b) {
    h2 t = __floats2half2_rn(a, b);
    return *reinterpret_cast<uint32_t*>(&t);
}
DEVFN float ex2f(float x) { float r; asm("ex2.approx.f32 %0, %1;" : "=f"(r) : "f"(x)); return r; }
DEVFN float clip10(float x) { return fminf(fmaxf(x, -10.f), 10.f); }
DEVFN float sigm(float x) { return 1.f / (1.f + __expf(-x)); }

DEVFN void cp16(void* s, const void* g) {
    unsigned sa = (unsigned)__cvta_generic_to_shared(s);
    asm volatile("cp.async.cg.shared.global [%0], [%1], 16;\n" :: "r"(sa), "l"(g));
}
DEVFN void cp_commit() { asm volatile("cp.async.commit_group;\n"); }
DEVFN void ldm4(uint32_t* r, const void* p) {
    unsigned a = (unsigned)__cvta_generic_to_shared(p);
    asm volatile("ldmatrix.sync.aligned.m8n8.x4.shared.b16 {%0,%1,%2,%3}, [%4];\n"
                 : "=r"(r[0]), "=r"(r[1]), "=r"(r[2]), "=r"(r[3]) : "r"(a));
}
// fp16 inputs, fp16 accumulators (2 regs)
DEVFN void mma_h(uint32_t* c, const uint32_t* a, const uint32_t* b) {
    asm volatile(
        "mma.sync.aligned.m16n8k16.row.col.f16.f16.f16.f16 "
        "{%0,%1}, {%2,%3,%4,%5}, {%6,%7}, {%0,%1};\n"
        : "+r"(c[0]), "+r"(c[1])
        : "r"(a[0]), "r"(a[1]), "r"(a[2]), "r"(a[3]), "r"(b[0]), "r"(b[1]));
}

// ---------------- merged prep kernel ----------------
constexpr int SG0 = N1 * DM;
constexpr int SG1 = N3 * DI;
constexpr int SG2 = N2 * DI;
constexpr int SG3 = N2;
constexpr int SG4 = ROWS * DM / 4;
constexpr int PREP_TOT = SG0 + SG1 + SG2 + SG3 + SG4;

__global__ void k_prep(const float* __restrict__ Win, const float* __restrict__ Wout,
                       const float* __restrict__ Wdt, const float* __restrict__ Wx,
                       const float* __restrict__ bdt, const float* __restrict__ x) {
    int i = blockIdx.x * 256 + threadIdx.x;
    if (i < SG0) { g_W1[i] = f2h(Win[i]); return; }
    i -= SG0;
    if (i < SG1) { g_W3[i] = f2h(Wout[i]); return; }
    i -= SG1;
    if (i < SG2) {
        int n = i / DI, k = i % DI;
        float v = 0.f;
        if (n < 1024)       v = Wdt[n * DI + k];
        else if (n < 1056)  v = Wx[(n - 1024) * DI + k];   // natural B | C order
        g_Wcat[i] = f2h(v);
        return;
    }
    i -= SG2;
    if (i < SG3) { g_b2[i] = (i < 1024) ? bdt[i] : 0.f; return; }
    i -= SG3;
    if (i < SG4) {
        float4 v = *reinterpret_cast<const float4*>(x + (size_t)i * 4);
        uint2 pk;
        pk.x = pack2h(clip10(v.x), clip10(v.y));
        pk.y = pack2h(clip10(v.z), clip10(v.w));
        *reinterpret_cast<uint2*>(g_xb + (size_t)i * 4) = pk;
    }
}

// =====================================================================
// HMMA GEMM — CTA 128x128, warp 32x64 (8 warps 4x2), fp16 accumulators,
// K-slab 64 (SCOLS=72), STG=3, 2 CTA/SM, single barrier per slab,
// fill-after-compute, exact commit accounting,
// REGISTER FRAGMENT DOUBLE-BUFFERING across kh blocks.
// =====================================================================
constexpr int STG = 3;
constexpr int KS = 64;                     // K-slab
constexpr int SCOLS = 72;                  // 64 + 8 pad
constexpr int A_STAGE = 128 * SCOLS;
constexpr int B_STAGE = 128 * SCOLS;
constexpr int SMEM_G = STG * (A_STAGE + B_STAGE) * 2;    // 110592 B

template <int SEL>
__global__ void __launch_bounds__(256, 2) k_gemm(const float* __restrict__ resid)
{
    constexpr int N = (SEL == 1) ? N1 : (SEL == 2) ? N2 : N3;
    constexpr int K = (SEL == 1) ? DM : DI;
    constexpr int KT = K / KS;             // 8 or 16
    const fp16* __restrict__ A  = (SEL == 1) ? g_xb : (SEL == 2) ? g_xc : g_y2;
    const fp16* __restrict__ Bw = (SEL == 1) ? g_W1 : (SEL == 2) ? g_Wcat : g_W3;

    extern __shared__ __align__(16) fp16 sm[];
    fp16* Asm = sm;
    fp16* Bsm = sm + STG * A_STAGE;

    const int tid = threadIdx.x, lane = tid & 31, warp = tid >> 5;
    const int wm = warp >> 1, wn = warp & 1;              // 4 x 2 warp grid
    const int m0 = blockIdx.y * 128, n0 = blockIdx.x * 128;
    const fp16* Ap = A + (size_t)m0 * K;
    const fp16* Bp = Bw + (size_t)n0 * K;

    uint32_t acc[2][8][2];
#pragma unroll
    for (int i = 0; i < 2; i++)
#pragma unroll
        for (int j = 0; j < 8; j++) { acc[i][j][0] = 0u; acc[i][j][1] = 0u; }

    auto fill = [&](int kt) {
        const int buf = kt % STG;
        fp16* As = Asm + buf * A_STAGE;
        fp16* Bs = Bsm + buf * B_STAGE;
#pragma unroll
        for (int i = 0; i < 4; i++) {                     // A: 1024 chunks
            int c = tid + i * 256;
            int row = c >> 3, col = (c & 7) << 3;
            cp16(As + row * SCOLS + col, Ap + (size_t)row * K + kt * KS + col);
        }
#pragma unroll
        for (int i = 0; i < 4; i++) {                     // B: 1024 chunks
            int c = tid + i * 256;
            int row = c >> 3, col = (c & 7) << 3;
            cp16(Bs + row * SCOLS + col, Bp + (size_t)row * K + kt * KS + col);
        }
        cp_commit();
    };

    fill(0); fill(1);

    // fragment double buffers
    uint32_t afb[2][2][4], bfb[2][8][2];

#pragma unroll 1
    for (int kt = 0; kt < KT; kt++) {
        asm volatile("cp.async.wait_group 1;\n");
        __syncthreads();                                  // single barrier per slab
        const int buf = kt % STG;
        const fp16* As = Asm + buf * A_STAGE;
        const fp16* Bs = Bsm + buf * B_STAGE;

        auto ldfrag = [&](int kh, uint32_t af[2][4], uint32_t bfr[8][2]) {
            const int kk = kh * 16;
#pragma unroll
            for (int mi = 0; mi < 2; mi++)
                ldm4(af[mi], As + (wm * 32 + mi * 16 + (lane & 15)) * SCOLS
                              + kk + ((lane >> 4) << 3));
#pragma unroll
            for (int ni2 = 0; ni2 < 4; ni2++) {
                uint32_t r[4];
                ldm4(r, Bs + (wn * 64 + ni2 * 16 + (lane & 15)) * SCOLS
                         + kk + ((lane >> 4) << 3));
                bfr[2 * ni2][0] = r[0]; bfr[2 * ni2][1] = r[2];
                bfr[2 * ni2 + 1][0] = r[1]; bfr[2 * ni2 + 1][1] = r[3];
            }
        };

        ldfrag(0, afb[0], bfb[0]);
#pragma unroll
        for (int kh = 0; kh < 4; kh++) {
            const int cur = kh & 1, nxt = cur ^ 1;
            if (kh < 3) ldfrag(kh + 1, afb[nxt], bfb[nxt]);   // overlap LDSM w/ HMMA
#pragma unroll
            for (int mi = 0; mi < 2; mi++)
#pragma unroll
                for (int ni = 0; ni < 8; ni++)
                    mma_h(acc[mi][ni], afb[cur][mi], bfb[cur][ni]);
        }
        // fill after compute; target buf (kt-1)%3 is free (top-barrier argument)
        if (kt + STG - 1 < KT) fill(kt + STG - 1);
        else cp_commit();
    }

    // epilogue
    const bool resHalf = (SEL == 1) && (n0 >= 1024);      // uniform per CTA
#pragma unroll
    for (int mi = 0; mi < 2; mi++) {
#pragma unroll
        for (int ni = 0; ni < 8; ni++) {
            int mA = m0 + wm * 32 + mi * 16 + (lane >> 2);
            int n = n0 + wn * 64 + ni * 8 + ((lane & 3) << 1);
#pragma unroll
            for (int h = 0; h < 2; h++) {
                int mm = mA + h * 8;
                size_t idx = (size_t)mm * N + n;
                if (SEL == 1) {
                    if (resHalf) {
                        float2 t = h2x(acc[mi][ni][h]);
                        float v0 = t.x * sigm(t.x), v1 = t.y * sigm(t.y);
                        *reinterpret_cast<uint32_t*>(g_xr + idx) = pack2h(v0, v1);
                    } else {
                        // x_p half: raw packed fp16 accumulator store
                        *reinterpret_cast<uint32_t*>(g_xr + idx) = acc[mi][ni][h];
                    }
                } else if (SEL == 2) {
                    float2 t = h2x(acc[mi][ni][h]);
                    float v0 = t.x + g_b2[n], v1 = t.y + g_b2[n + 1];
                    *reinterpret_cast<uint32_t*>(g_dtbc + idx) = pack2h(v0, v1);
                    if (n >= 1024 && n < 1056)
                        *reinterpret_cast<float2*>(&g_bc[(size_t)mm * 32 + (n - 1024)]) =
                            make_float2(v0, v1);
                } else {
                    float2 t = h2x(acc[mi][ni][h]);
                    float x0 = clip10(resid[idx]);
                    float x1 = clip10(resid[idx + 1]);
                    *reinterpret_cast<float2*>(g_opre + idx) =
                        make_float2(t.x + x0, t.y + x1);
                }
            }
        }
    }
}

// ---------------- causal depthwise conv(4) + SiLU, 4 di / thread --------
__global__ void k_conv(const float* __restrict__ cw, const float* __restrict__ cb) {
    int idx = blockIdx.x * 256 + threadIdx.x;
    if (idx >= ROWS * (DI / 4)) return;
    int di4 = (idx & 255) * 4;
    size_t row = (size_t)(idx >> 8);
    int t = (int)(row % SEQ);

    float acc[4] = { cb[di4], cb[di4 + 1], cb[di4 + 2], cb[di4 + 3] };
    float4 w0 = *reinterpret_cast<const float4*>(cw + (di4 + 0) * 4);
    float4 w1 = *reinterpret_cast<const float4*>(cw + (di4 + 1) * 4);
    float4 w2 = *reinterpret_cast<const float4*>(cw + (di4 + 2) * 4);
    float4 w3 = *reinterpret_cast<const float4*>(cw + (di4 + 3) * 4);
    const float* wv[4] = { (const float*)&w0, (const float*)&w1,
                           (const float*)&w2, (const float*)&w3 };
#pragma unroll
    for (int k = 0; k < 4; k++) {
        if (t - 3 + k < 0) continue;
        uint2 raw = *reinterpret_cast<const uint2*>(&g_xr[(row - 3 + k) * N1 + di4]);
        float2 lo = h2x(raw.x), hi = h2x(raw.y);
        acc[0] = fmaf(wv[0][k], lo.x, acc[0]);
        acc[1] = fmaf(wv[1][k], lo.y, acc[1]);
        acc[2] = fmaf(wv[2][k], hi.x, acc[2]);
        acc[3] = fmaf(wv[3][k], hi.y, acc[3]);
    }
#pragma unroll
    for (int j = 0; j < 4; j++) acc[j] = acc[j] * sigm(acc[j]);
    uint2 pk;
    pk.x = pack2h(acc[0], acc[1]);
    pk.y = pack2h(acc[2], acc[3]);
    *reinterpret_cast<uint2*>(&g_xc[row * DI + di4]) = pk;
}

// =====================================================================
// Selective scan: 64-thread blocks (16 di x 4 q), 1024 blocks,
// cp.async ring, f32 B/C, pre-silu'ed res, fused output. Chunk 16 t.
// Per t in smem (224B): dt 32B | u 32B | B 64B f32 | C 64B f32 | res 32B
// =====================================================================
constexpr int SC_CHUNK = 16;
constexpr int SC_RING = 4;
constexpr int SC_TB = 224;
constexpr int SC_CHB = SC_CHUNK * SC_TB;                  // 3584 B
constexpr int SC_NCH = SEQ / SC_CHUNK;                    // 128

__global__ void __launch_bounds__(64) k_scan(const float* __restrict__ A_log,
                                             const float* __restrict__ Dp) {
    __shared__ __align__(16) char sbuf[SC_RING * SC_CHB]; // 14336 B

    const int tid = threadIdx.x;
    const int b = blockIdx.x >> 6;
    const int diblk = blockIdx.x & 63;
    const int q = tid & 3;
    const int dil = tid >> 2;                             // 0..15
    const int di = diblk * 16 + dil;
    const float LOG2E = 1.4426950408889634f;

    float A2[4];
#pragma unroll
    for (int j = 0; j < 4; j++) A2[j] = A_log[q * 4 + j] * LOG2E;
    const float Dv = Dp[di];
    const size_t rb = (size_t)b * SEQ;

    auto fill = [&](int c) {
#pragma unroll
        for (int r = 0; r < 4; r++) {
            int cc = tid + r * 64;                        // 0..255
            if (cc < 14 * SC_CHUNK) {                     // 14 cp16 per t
                int t = cc / 14, part = cc % 14;
                size_t row = rb + (size_t)c * SC_CHUNK + t;
                char* dst = sbuf + (c & (SC_RING - 1)) * SC_CHB + t * SC_TB;
                const char* src;
                if (part < 2) {
                    dst += part * 16;
                    src = (const char*)&g_dtbc[row * N2 + diblk * 16] + part * 16;
                } else if (part < 4) {
                    dst += 32 + (part - 2) * 16;
                    src = (const char*)&g_xc[row * DI + diblk * 16] + (part - 2) * 16;
                } else if (part < 12) {
                    dst += 64 + (part - 4) * 16;
                    src = (const char*)&g_bc[row * 32] + (part - 4) * 16;
                } else {
                    dst += 192 + (part - 12) * 16;
                    src = (const char*)&g_xr[row * N1 + 1024 + diblk * 16] + (part - 12) * 16;
                }
                cp16(dst, src);
            }
        }
        cp_commit();
    };

    fill(0); fill(1); fill(2);

    float s0 = 0.f, s1 = 0.f, s2 = 0.f, s3 = 0.f;

#pragma unroll 1
    for (int c = 0; c < SC_NCH; c++) {
        asm volatile("cp.async.wait_group %0;\n" :: "n"(2));
        __syncthreads();
        const char* base = sbuf + (c & (SC_RING - 1)) * SC_CHB;
#pragma unroll
        for (int tl = 0; tl < SC_CHUNK; tl++) {
            const char* p = base + tl * SC_TB;
            float dt = h2f(reinterpret_cast<const fp16*>(p)[dil]);
            float u  = h2f(reinterpret_cast<const fp16*>(p + 32)[dil]);
            float4 B4 = *reinterpret_cast<const float4*>(p + 64 + q * 16);
            float4 C4 = *reinterpret_cast<const float4*>(p + 128 + q * 16);
            float du = dt * u;

            float acc;
            s0 = fmaf(ex2f(dt * A2[0]), s0, du * B4.x); acc = s0 * C4.x;
            s1 = fmaf(ex2f(dt * A2[1]), s1, du * B4.y); acc = fmaf(s1, C4.y, acc);
            s2 = fmaf(ex2f(dt * A2[2]), s2, du * B4.z); acc = fmaf(s2, C4.z, acc);
            s3 = fmaf(ex2f(dt * A2[3]), s3, du * B4.w); acc = fmaf(s3, C4.w, acc);

            acc += __shfl_xor_sync(0xffffffffu, acc, 1);
            acc += __shfl_xor_sync(0xffffffffu, acc, 2);
            if (q == 0) {
                float rp = h2f(reinterpret_cast<const fp16*>(p + 192)[dil]);  // pre-silu'ed
                g_y2[(rb + (size_t)c * SC_CHUNK + tl) * DI + di] =
                    f2h(fmaf(u, Dv, acc) * rp);
            }
        }
        if (c + 3 < SC_NCH) fill(c + 3);
        else cp_commit();
    }
}

// ---------------- LayerNorm ----------------
__global__ void __launch_bounds__(256) k_ln(const float* __restrict__ gam,
                                            const float* __restrict__ bet,
                                            float* __restrict__ out) {
    int w = (blockIdx.x * 256 + threadIdx.x) >> 5;
    int lane = threadIdx.x & 31;
    if (w >= ROWS) return;
    const float* r = g_opre + (size_t)w * DM;
    float v[16], s = 0.f, ss = 0.f;
#pragma unroll
    for (int i = 0; i < 16; i++) {
        v[i] = r[i * 32 + lane];
        s += v[i];
        ss = fmaf(v[i], v[i], ss);
    }
#pragma unroll
    for (int o = 16; o; o >>= 1) {
        s += __shfl_xor_sync(0xffffffffu, s, o);
        ss += __shfl_xor_sync(0xffffffffu, ss, o);
    }
    float mu = s * (1.f / 512.f);
    float var = ss * (1.f / 512.f) - mu * mu;
    float rstd = rsqrtf(var + 1e-5f);
#pragma unroll
    for (int i = 0; i < 16; i++) {
        int c = i * 32 + lane;
        out[(size_t)w * DM + c] = (v[i] - mu) * rstd * gam[c] + bet[c];
    }
}

// ---------------- launch ----------------
extern "C" void kernel_launch(void* const* d_in, const int* in_sizes, int n_in,
                              void* d_out, int out_size) {
    const float* x      = (const float*)d_in[0];
    const float* W_in   = (const float*)d_in[1];
    const float* conv_w = (const float*)d_in[2];
    const float* conv_b = (const float*)d_in[3];
    const float* W_x    = (const float*)d_in[4];
    const float* W_dt   = (const float*)d_in[5];
    const float* b_dt   = (const float*)d_in[6];
    const float* A_log  = (const float*)d_in[7];
    const float* Dp     = (const float*)d_in[8];
    const float* W_out  = (const float*)d_in[9];
    const float* ln_g   = (const float*)d_in[10];
    const float* ln_b   = (const float*)d_in[11];
    float* out = (float*)d_out;

    static bool attr_done = false;
    if (!attr_done) {
        cudaFuncSetAttribute(k_gemm<1>, cudaFuncAttributeMaxDynamicSharedMemorySize, SMEM_G);
        cudaFuncSetAttribute(k_gemm<2>, cudaFuncAttributeMaxDynamicSharedMemorySize, SMEM_G);
        cudaFuncSetAttribute(k_gemm<3>, cudaFuncAttributeMaxDynamicSharedMemorySize, SMEM_G);
        attr_done = true;
    }

    // 1: prep
    k_prep<<<(PREP_TOT + 255) / 256, 256>>>(W_in, W_out, W_dt, W_x, b_dt, x);
    // 2: GEMM1 [32768,2048] frag-dbuf (res half pre-silu'ed, x_p raw-store)
    k_gemm<1><<<dim3(N1 / 128, ROWS / 128), 256, SMEM_G>>>(nullptr);
    // 3: conv
    k_conv<<<ROWS * (DI / 4) / 256, 256>>>(conv_w, conv_b);
    // 4: GEMM2 [32768,1152] frag-dbuf (+f32 BC side-store)  <-- ncu window
    k_gemm<2><<<dim3(N2 / 128, ROWS / 128), 256, SMEM_G>>>(nullptr);
    // 5: scan (+ fused mulsilu) -> g_y2
    k_scan<<<B_SZ * 64, 64>>>(A_log, Dp);
    // 6: GEMM3 [32768,512] frag-dbuf + f32 residual
    k_gemm<3><<<dim3(N3 / 128, ROWS / 128), 256, SMEM_G>>>(x);
    // 7: LN
    k_ln<<<(ROWS * 32 + 255) / 256, 256>>>(ln_g, ln_b, out);
}

// round 16
// speedup vs baseline: 1.0382x; 1.0382x over previous
#include <cuda_runtime.h>
#include <cuda_fp16.h>
#include <cstdint>

using fp16 = __half;
using h2 = __half2;

#define DEVFN __device__ __forceinline__

// ---------------- problem sizes ----------------
constexpr int B_SZ = 16, SEQ = 2048, DM = 512, DI = 1024, DS = 16;
constexpr int ROWS = B_SZ * SEQ;           // 32768
constexpr int HR = ROWS / 2;               // 16384 rows per half-batch
constexpr int N1 = 2 * DI;                 // 2048
constexpr int N2 = 1152;                   // 1024 dt + 32 (B|C) + 96 pad
constexpr int N3 = DM;                     // 512

// ---------------- scratch globals (fp16 intermediates) ----------------
__device__ __align__(256) fp16  g_xb  [(size_t)ROWS * DM];
__device__ __align__(256) fp16  g_W1  [(size_t)N1 * DM];
__device__ __align__(256) fp16  g_xr  [(size_t)ROWS * N1];   // x_p | silu(res)
__device__ __align__(256) fp16  g_xc  [(size_t)ROWS * DI];
__device__ __align__(256) fp16  g_Wcat[(size_t)N2 * DI];
__device__ __align__(256) float g_b2  [N2];
__device__ __align__(256) fp16  g_dtbc[(size_t)ROWS * N2];
__device__ __align__(256) float g_bc  [(size_t)ROWS * 32];   // B|C f32 for scan
__device__ __align__(256) fp16  g_y2  [(size_t)ROWS * DI];
__device__ __align__(256) fp16  g_W3  [(size_t)N3 * DI];
__device__ __align__(256) float g_opre[(size_t)ROWS * DM];

// ---------------- helpers ----------------
DEVFN float h2f(fp16 v) { return __half2float(v); }
DEVFN fp16  f2h(float v) { return __float2half(v); }
DEVFN float2 h2x(uint32_t u) { h2 t = *reinterpret_cast<h2*>(&u); return __half22float2(t); }
DEVFN uint32_t pack2h(float a, float b) {
    h2 t = __floats2half2_rn(a, b);
    return *reinterpret_cast<uint32_t*>(&t);
}
DEVFN float ex2f(float x) { float r; asm("ex2.approx.f32 %0, %1;" : "=f"(r) : "f"(x)); return r; }
DEVFN float clip10(float x) { return fminf(fmaxf(x, -10.f), 10.f); }
DEVFN float sigm(float x) { return 1.f / (1.f + __expf(-x)); }

DEVFN void cp16(void* s, const void* g) {
    unsigned sa = (unsigned)__cvta_generic_to_shared(s);
    asm volatile("cp.async.cg.shared.global [%0], [%1], 16;\n" :: "r"(sa), "l"(g));
}
DEVFN void cp_commit() { asm volatile("cp.async.commit_group;\n"); }
DEVFN void ldm4(uint32_t* r, const void* p) {
    unsigned a = (unsigned)__cvta_generic_to_shared(p);
    asm volatile("ldmatrix.sync.aligned.m8n8.x4.shared.b16 {%0,%1,%2,%3}, [%4];\n"
                 : "=r"(r[0]), "=r"(r[1]), "=r"(r[2]), "=r"(r[3]) : "r"(a));
}
// fp16 inputs, fp16 accumulators (2 regs)
DEVFN void mma_h(uint32_t* c, const uint32_t* a, const uint32_t* b) {
    asm volatile(
        "mma.sync.aligned.m16n8k16.row.col.f16.f16.f16.f16 "
        "{%0,%1}, {%2,%3,%4,%5}, {%6,%7}, {%0,%1};\n"
        : "+r"(c[0]), "+r"(c[1])
        : "r"(a[0]), "r"(a[1]), "r"(a[2]), "r"(a[3]), "r"(b[0]), "r"(b[1]));
}

// ---------------- merged prep kernel (whole batch) ----------------
constexpr int SG0 = N1 * DM;
constexpr int SG1 = N3 * DI;
constexpr int SG2 = N2 * DI;
constexpr int SG3 = N2;
constexpr int SG4 = ROWS * DM / 4;
constexpr int PREP_TOT = SG0 + SG1 + SG2 + SG3 + SG4;

__global__ void k_prep(const float* __restrict__ Win, const float* __restrict__ Wout,
                       const float* __restrict__ Wdt, const float* __restrict__ Wx,
                       const float* __restrict__ bdt, const float* __restrict__ x) {
    int i = blockIdx.x * 256 + threadIdx.x;
    if (i < SG0) { g_W1[i] = f2h(Win[i]); return; }
    i -= SG0;
    if (i < SG1) { g_W3[i] = f2h(Wout[i]); return; }
    i -= SG1;
    if (i < SG2) {
        int n = i / DI, k = i % DI;
        float v = 0.f;
        if (n < 1024)       v = Wdt[n * DI + k];
        else if (n < 1056)  v = Wx[(n - 1024) * DI + k];   // natural B | C order
        g_Wcat[i] = f2h(v);
        return;
    }
    i -= SG2;
    if (i < SG3) { g_b2[i] = (i < 1024) ? bdt[i] : 0.f; return; }
    i -= SG3;
    if (i < SG4) {
        float4 v = *reinterpret_cast<const float4*>(x + (size_t)i * 4);
        uint2 pk;
        pk.x = pack2h(clip10(v.x), clip10(v.y));
        pk.y = pack2h(clip10(v.z), clip10(v.w));
        *reinterpret_cast<uint2*>(g_xb + (size_t)i * 4) = pk;
    }
}

// =====================================================================
// HMMA GEMM — CTA 128x128, warp 32x64 (8 warps 4x2), fp16 accumulators,
// K-slab 64 (SCOLS=72), STG=3, 2 CTA/SM, single barrier per slab,
// fill-after-compute, exact commit accounting. r0 = row offset (half-batch).
// =====================================================================
constexpr int STG = 3;
constexpr int KS = 64;
constexpr int SCOLS = 72;
constexpr int A_STAGE = 128 * SCOLS;
constexpr int B_STAGE = 128 * SCOLS;
constexpr int SMEM_G = STG * (A_STAGE + B_STAGE) * 2;    // 110592 B

template <int SEL>
__global__ void __launch_bounds__(256, 2) k_gemm(const float* __restrict__ resid, int r0)
{
    constexpr int N = (SEL == 1) ? N1 : (SEL == 2) ? N2 : N3;
    constexpr int K = (SEL == 1) ? DM : DI;
    constexpr int KT = K / KS;
    const fp16* __restrict__ A  = (SEL == 1) ? g_xb : (SEL == 2) ? g_xc : g_y2;
    const fp16* __restrict__ Bw = (SEL == 1) ? g_W1 : (SEL == 2) ? g_Wcat : g_W3;

    extern __shared__ __align__(16) fp16 sm[];
    fp16* Asm = sm;
    fp16* Bsm = sm + STG * A_STAGE;

    const int tid = threadIdx.x, lane = tid & 31, warp = tid >> 5;
    const int wm = warp >> 1, wn = warp & 1;              // 4 x 2 warp grid
    const int m0 = r0 + blockIdx.y * 128, n0 = blockIdx.x * 128;
    const fp16* Ap = A + (size_t)m0 * K;
    const fp16* Bp = Bw + (size_t)n0 * K;

    uint32_t acc[2][8][2];
#pragma unroll
    for (int i = 0; i < 2; i++)
#pragma unroll
        for (int j = 0; j < 8; j++) { acc[i][j][0] = 0u; acc[i][j][1] = 0u; }

    auto fill = [&](int kt) {
        const int buf = kt % STG;
        fp16* As = Asm + buf * A_STAGE;
        fp16* Bs = Bsm + buf * B_STAGE;
#pragma unroll
        for (int i = 0; i < 4; i++) {
            int c = tid + i * 256;
            int row = c >> 3, col = (c & 7) << 3;
            cp16(As + row * SCOLS + col, Ap + (size_t)row * K + kt * KS + col);
        }
#pragma unroll
        for (int i = 0; i < 4; i++) {
            int c = tid + i * 256;
            int row = c >> 3, col = (c & 7) << 3;
            cp16(Bs + row * SCOLS + col, Bp + (size_t)row * K + kt * KS + col);
        }
        cp_commit();
    };

    fill(0); fill(1);

    uint32_t afb[2][2][4], bfb[2][8][2];

#pragma unroll 1
    for (int kt = 0; kt < KT; kt++) {
        asm volatile("cp.async.wait_group 1;\n");
        __syncthreads();
        const int buf = kt % STG;
        const fp16* As = Asm + buf * A_STAGE;
        const fp16* Bs = Bsm + buf * B_STAGE;

        auto ldfrag = [&](int kh, uint32_t af[2][4], uint32_t bfr[8][2]) {
            const int kk = kh * 16;
#pragma unroll
            for (int mi = 0; mi < 2; mi++)
                ldm4(af[mi], As + (wm * 32 + mi * 16 + (lane & 15)) * SCOLS
                              + kk + ((lane >> 4) << 3));
#pragma unroll
            for (int ni2 = 0; ni2 < 4; ni2++) {
                uint32_t r[4];
                ldm4(r, Bs + (wn * 64 + ni2 * 16 + (lane & 15)) * SCOLS
                         + kk + ((lane >> 4) << 3));
                bfr[2 * ni2][0] = r[0]; bfr[2 * ni2][1] = r[2];
                bfr[2 * ni2 + 1][0] = r[1]; bfr[2 * ni2 + 1][1] = r[3];
            }
        };

        ldfrag(0, afb[0], bfb[0]);
#pragma unroll
        for (int kh = 0; kh < 4; kh++) {
            const int cur = kh & 1, nxt = cur ^ 1;
            if (kh < 3) ldfrag(kh + 1, afb[nxt], bfb[nxt]);
#pragma unroll
            for (int mi = 0; mi < 2; mi++)
#pragma unroll
                for (int ni = 0; ni < 8; ni++)
                    mma_h(acc[mi][ni], afb[cur][mi], bfb[cur][ni]);
        }
        if (kt + STG - 1 < KT) fill(kt + STG - 1);
        else cp_commit();
    }

    // epilogue
    const bool resHalf = (SEL == 1) && (n0 >= 1024);
#pragma unroll
    for (int mi = 0; mi < 2; mi++) {
#pragma unroll
        for (int ni = 0; ni < 8; ni++) {
            int mA = m0 + wm * 32 + mi * 16 + (lane >> 2);
            int n = n0 + wn * 64 + ni * 8 + ((lane & 3) << 1);
#pragma unroll
            for (int h = 0; h < 2; h++) {
                int mm = mA + h * 8;
                size_t idx = (size_t)mm * N + n;
                if (SEL == 1) {
                    if (resHalf) {
                        float2 t = h2x(acc[mi][ni][h]);
                        float v0 = t.x * sigm(t.x), v1 = t.y * sigm(t.y);
                        *reinterpret_cast<uint32_t*>(g_xr + idx) = pack2h(v0, v1);
                    } else {
                        *reinterpret_cast<uint32_t*>(g_xr + idx) = acc[mi][ni][h];
                    }
                } else if (SEL == 2) {
                    float2 t = h2x(acc[mi][ni][h]);
                    float v0 = t.x + g_b2[n], v1 = t.y + g_b2[n + 1];
                    *reinterpret_cast<uint32_t*>(g_dtbc + idx) = pack2h(v0, v1);
                    if (n >= 1024 && n < 1056)
                        *reinterpret_cast<float2*>(&g_bc[(size_t)mm * 32 + (n - 1024)]) =
                            make_float2(v0, v1);
                } else {
                    float2 t = h2x(acc[mi][ni][h]);
                    float x0 = clip10(resid[idx]);
                    float x1 = clip10(resid[idx + 1]);
                    *reinterpret_cast<float2*>(g_opre + idx) =
                        make_float2(t.x + x0, t.y + x1);
                }
            }
        }
    }
}

// ---------------- causal depthwise conv(4) + SiLU, 4 di / thread --------
__global__ void k_conv(const float* __restrict__ cw, const float* __restrict__ cb, int r0) {
    int idx = blockIdx.x * 256 + threadIdx.x;
    if (idx >= HR * (DI / 4)) return;
    int di4 = (idx & 255) * 4;
    size_t row = (size_t)r0 + (size_t)(idx >> 8);
    int t = (int)(row % SEQ);

    float acc[4] = { cb[di4], cb[di4 + 1], cb[di4 + 2], cb[di4 + 3] };
    float4 w0 = *reinterpret_cast<const float4*>(cw + (di4 + 0) * 4);
    float4 w1 = *reinterpret_cast<const float4*>(cw + (di4 + 1) * 4);
    float4 w2 = *reinterpret_cast<const float4*>(cw + (di4 + 2) * 4);
    float4 w3 = *reinterpret_cast<const float4*>(cw + (di4 + 3) * 4);
    const float* wv[4] = { (const float*)&w0, (const float*)&w1,
                           (const float*)&w2, (const float*)&w3 };
#pragma unroll
    for (int k = 0; k < 4; k++) {
        if (t - 3 + k < 0) continue;
        uint2 raw = *reinterpret_cast<const uint2*>(&g_xr[(row - 3 + k) * N1 + di4]);
        float2 lo = h2x(raw.x), hi = h2x(raw.y);
        acc[0] = fmaf(wv[0][k], lo.x, acc[0]);
        acc[1] = fmaf(wv[1][k], lo.y, acc[1]);
        acc[2] = fmaf(wv[2][k], hi.x, acc[2]);
        acc[3] = fmaf(wv[3][k], hi.y, acc[3]);
    }
#pragma unroll
    for (int j = 0; j < 4; j++) acc[j] = acc[j] * sigm(acc[j]);
    uint2 pk;
    pk.x = pack2h(acc[0], acc[1]);
    pk.y = pack2h(acc[2], acc[3]);
    *reinterpret_cast<uint2*>(&g_xc[row * DI + di4]) = pk;
}

// =====================================================================
// Selective scan: 64-thread blocks (16 di x 4 q), half-batch (512 blocks),
// cp.async ring, f32 B/C, pre-silu'ed res, fused output. Chunk 16 t.
// =====================================================================
constexpr int SC_CHUNK = 16;
constexpr int SC_RING = 4;
constexpr int SC_TB = 224;
constexpr int SC_CHB = SC_CHUNK * SC_TB;
constexpr int SC_NCH = SEQ / SC_CHUNK;

__global__ void __launch_bounds__(64) k_scan(const float* __restrict__ A_log,
                                             const float* __restrict__ Dp, int b0) {
    __shared__ __align__(16) char sbuf[SC_RING * SC_CHB];

    const int tid = threadIdx.x;
    const int b = b0 + (blockIdx.x >> 6);
    const int diblk = blockIdx.x & 63;
    const int q = tid & 3;
    const int dil = tid >> 2;
    const int di = diblk * 16 + dil;
    const float LOG2E = 1.4426950408889634f;

    float A2[4];
#pragma unroll
    for (int j = 0; j < 4; j++) A2[j] = A_log[q * 4 + j] * LOG2E;
    const float Dv = Dp[di];
    const size_t rb = (size_t)b * SEQ;

    auto fill = [&](int c) {
#pragma unroll
        for (int r = 0; r < 4; r++) {
            int cc = tid + r * 64;
            if (cc < 14 * SC_CHUNK) {
                int t = cc / 14, part = cc % 14;
                size_t row = rb + (size_t)c * SC_CHUNK + t;
                char* dst = sbuf + (c & (SC_RING - 1)) * SC_CHB + t * SC_TB;
                const char* src;
                if (part < 2) {
                    dst += part * 16;
                    src = (const char*)&g_dtbc[row * N2 + diblk * 16] + part * 16;
                } else if (part < 4) {
                    dst += 32 + (part - 2) * 16;
                    src = (const char*)&g_xc[row * DI + diblk * 16] + (part - 2) * 16;
                } else if (part < 12) {
                    dst += 64 + (part - 4) * 16;
                    src = (const char*)&g_bc[row * 32] + (part - 4) * 16;
                } else {
                    dst += 192 + (part - 12) * 16;
                    src = (const char*)&g_xr[row * N1 + 1024 + diblk * 16] + (part - 12) * 16;
                }
                cp16(dst, src);
            }
        }
        cp_commit();
    };

    fill(0); fill(1); fill(2);

    float s0 = 0.f, s1 = 0.f, s2 = 0.f, s3 = 0.f;

#pragma unroll 1
    for (int c = 0; c < SC_NCH; c++) {
        asm volatile("cp.async.wait_group %0;\n" :: "n"(2));
        __syncthreads();
        const char* base = sbuf + (c & (SC_RING - 1)) * SC_CHB;
#pragma unroll
        for (int tl = 0; tl < SC_CHUNK; tl++) {
            const char* p = base + tl * SC_TB;
            float dt = h2f(reinterpret_cast<const fp16*>(p)[dil]);
            float u  = h2f(reinterpret_cast<const fp16*>(p + 32)[dil]);
            float4 B4 = *reinterpret_cast<const float4*>(p + 64 + q * 16);
            float4 C4 = *reinterpret_cast<const float4*>(p + 128 + q * 16);
            float du = dt * u;

            float acc;
            s0 = fmaf(ex2f(dt * A2[0]), s0, du * B4.x); acc = s0 * C4.x;
            s1 = fmaf(ex2f(dt * A2[1]), s1, du * B4.y); acc = fmaf(s1, C4.y, acc);
            s2 = fmaf(ex2f(dt * A2[2]), s2, du * B4.z); acc = fmaf(s2, C4.z, acc);
            s3 = fmaf(ex2f(dt * A2[3]), s3, du * B4.w); acc = fmaf(s3, C4.w, acc);

            acc += __shfl_xor_sync(0xffffffffu, acc, 1);
            acc += __shfl_xor_sync(0xffffffffu, acc, 2);
            if (q == 0) {
                float rp = h2f(reinterpret_cast<const fp16*>(p + 192)[dil]);
                g_y2[(rb + (size_t)c * SC_CHUNK + tl) * DI + di] =
                    f2h(fmaf(u, Dv, acc) * rp);
            }
        }
        if (c + 3 < SC_NCH) fill(c + 3);
        else cp_commit();
    }
}

// ---------------- LayerNorm (half-batch) ----------------
__global__ void __launch_bounds__(256) k_ln(const float* __restrict__ gam,
                                            const float* __restrict__ bet,
                                            float* __restrict__ out, int r0) {
    int wl = (blockIdx.x * 256 + threadIdx.x) >> 5;
    int lane = threadIdx.x & 31;
    if (wl >= HR) return;
    size_t w = (size_t)r0 + wl;
    const float* r = g_opre + w * DM;
    float v[16], s = 0.f, ss = 0.f;
#pragma unroll
    for (int i = 0; i < 16; i++) {
        v[i] = r[i * 32 + lane];
        s += v[i];
        ss = fmaf(v[i], v[i], ss);
    }
#pragma unroll
    for (int o = 16; o; o >>= 1) {
        s += __shfl_xor_sync(0xffffffffu, s, o);
        ss += __shfl_xor_sync(0xffffffffu, ss, o);
    }
    float mu = s * (1.f / 512.f);
    float var = ss * (1.f / 512.f) - mu * mu;
    float rstd = rsqrtf(var + 1e-5f);
#pragma unroll
    for (int i = 0; i < 16; i++) {
        int c = i * 32 + lane;
        out[w * DM + c] = (v[i] - mu) * rstd * gam[c] + bet[c];
    }
}

// ---------------- launch: two-stream split-batch overlap ----------------
extern "C" void kernel_launch(void* const* d_in, const int* in_sizes, int n_in,
                              void* d_out, int out_size) {
    const float* x      = (const float*)d_in[0];
    const float* W_in   = (const float*)d_in[1];
    const float* conv_w = (const float*)d_in[2];
    const float* conv_b = (const float*)d_in[3];
    const float* W_x    = (const float*)d_in[4];
    const float* W_dt   = (const float*)d_in[5];
    const float* b_dt   = (const float*)d_in[6];
    const float* A_log  = (const float*)d_in[7];
    const float* Dp     = (const float*)d_in[8];
    const float* W_out  = (const float*)d_in[9];
    const float* ln_g   = (const float*)d_in[10];
    const float* ln_b   = (const float*)d_in[11];
    float* out = (float*)d_out;

    static cudaStream_t sB = nullptr;
    static cudaEvent_t evF = nullptr, evJ = nullptr;
    static bool init_done = false;
    if (!init_done) {
        cudaFuncSetAttribute(k_gemm<1>, cudaFuncAttributeMaxDynamicSharedMemorySize, SMEM_G);
        cudaFuncSetAttribute(k_gemm<2>, cudaFuncAttributeMaxDynamicSharedMemorySize, SMEM_G);
        cudaFuncSetAttribute(k_gemm<3>, cudaFuncAttributeMaxDynamicSharedMemorySize, SMEM_G);
        cudaStreamCreateWithFlags(&sB, cudaStreamNonBlocking);
        cudaEventCreateWithFlags(&evF, cudaEventDisableTiming);
        cudaEventCreateWithFlags(&evJ, cudaEventDisableTiming);
        init_done = true;
    }

    // prep (whole batch) on the main stream
    k_prep<<<(PREP_TOT + 255) / 256, 256>>>(W_in, W_out, W_dt, W_x, b_dt, x);
    cudaEventRecord(evF, 0);
    cudaStreamWaitEvent(sB, evF, 0);

    auto chain = [&](int r0, cudaStream_t st) {
        // GEMM1 [HR,2048]
        k_gemm<1><<<dim3(N1 / 128, HR / 128), 256, SMEM_G, st>>>(nullptr, r0);
        // conv
        k_conv<<<HR * (DI / 4) / 256, 256, 0, st>>>(conv_w, conv_b, r0);
        // GEMM2 [HR,1152]
        k_gemm<2><<<dim3(N2 / 128, HR / 128), 256, SMEM_G, st>>>(nullptr, r0);
        // scan (+ fused mulsilu)
        k_scan<<<(B_SZ / 2) * 64, 64, 0, st>>>(A_log, Dp, r0 / SEQ);
        // GEMM3 [HR,512] + f32 residual
        k_gemm<3><<<dim3(N3 / 128, HR / 128), 256, SMEM_G, st>>>(x, r0);
        // LN
        k_ln<<<HR * 32 / 256, 256, 0, st>>>(ln_g, ln_b, out, r0);
    };

    chain(0, (cudaStream_t)0);   // half A on main stream
    chain(HR, sB);               // half B on side stream (overlaps)

    cudaEventRecord(evJ, sB);
    cudaStreamWaitEvent((cudaStream_t)0, evJ, 0);
}